// round 13
// baseline (speedup 1.0000x reference)
#include <cuda_runtime.h>
#include <cuda_bf16.h>
#include <math_constants.h>

// RoI max pooling (Caffe-style), bit-matching the JAX/XLA:CPU reference.
// VERIFIED ARITHMETIC (R6, rel_err==0.0) — do not alter:
//   rs*    = rintf(__fmul_rn(coord, scale))
//   bh/bw  = __fmul_rn(roi_extent, 1.0f/7.0f)   (XLA fast-math reciprocal form)
//   hstart = floorf(__fmul_rn(ph, bh)) + rsh ; hend = ceilf(__fmul_rn(ph+1,bh)) + rsh
//   clip to [0,64]; empty bin (hend<=hstart || wend<=wstart) -> 0.
//
// Kernel 1: transpose [B,C,H*W] -> [B,H*W,C] (channel-fastest scratch).
// Kernel 2: pool with COLMAX FACTORIZATION: block = (n, ph, channel-half).
//   Phase A: colmax[col][c4] over the bin's rows — each window element
//            loaded exactly ONCE (removes R12's ~1.8x pw-overlap traffic).
//   Phase B: 7 pw windows reduce over smem colmax.
// All bounds block-uniform -> zero divergence; loads 512B-contiguous/warp.

#define CROP_H 7
#define CROP_W 7
#define NROI   128
#define HH     64
#define WW     64
#define HW     (HH * WW)
#define CC     256
#define BB     4

__device__ float g_dt[BB * HW * CC];   // 16 MB transposed data

// ---------------- transpose: [b][c][hw] -> [b][hw][c] ----------------
__global__ __launch_bounds__(256)
void transpose_kernel(const float* __restrict__ in)
{
    __shared__ float tile[32][33];
    int b   = blockIdx.z;
    int hw0 = blockIdx.x * 32;
    int c0  = blockIdx.y * 32;

    const float* src = in   + (size_t)b * CC * HW;
    float*       dst = g_dt + (size_t)b * HW * CC;

    #pragma unroll
    for (int i = threadIdx.y; i < 32; i += 8)
        tile[i][threadIdx.x] = src[(size_t)(c0 + i) * HW + hw0 + threadIdx.x];
    __syncthreads();
    #pragma unroll
    for (int i = threadIdx.y; i < 32; i += 8)
        dst[(size_t)(hw0 + i) * CC + c0 + threadIdx.x] = tile[threadIdx.x][i];
}

// ------ pool: block = (ph, chalf) x n; 128 thr = 32 c4-lanes x 4 slices ------
__global__ __launch_bounds__(128)
void pool_kernel(const float* __restrict__ rois,
                 const int*   __restrict__ roibatches,
                 const float* __restrict__ scale_ptr,
                 float* __restrict__ out)
{
    __shared__ float4 sm[WW][32];      // colmax[col - wlo][c4]  (32 KB)

    int ph    = blockIdx.x >> 1;       // 0..6
    int chalf = blockIdx.x & 1;        // 0..1
    int n     = blockIdx.y;

    int c4    = threadIdx.x & 31;      // 0..31 (channel quad within half)
    int slice = threadIdx.x >> 5;      // 0..3  (column slice)

    // ---- geometry (uniform across block; verified arithmetic) ----
    float scale = __ldg(scale_ptr);
    float x1 = __ldg(&rois[n * 4 + 0]);
    float y1 = __ldg(&rois[n * 4 + 1]);
    float x2 = __ldg(&rois[n * 4 + 2]);
    float y2 = __ldg(&rois[n * 4 + 3]);

    int rsw = (int)rintf(__fmul_rn(x1, scale));
    int rsh = (int)rintf(__fmul_rn(y1, scale));
    int rew = (int)rintf(__fmul_rn(x2, scale));
    int reh = (int)rintf(__fmul_rn(y2, scale));

    float roi_h = (float)max(reh - rsh + 1, 1);
    float roi_w = (float)max(rew - rsw + 1, 1);
    const float RCP7 = 1.0f / 7.0f;
    float bh = __fmul_rn(roi_h, RCP7);
    float bw = __fmul_rn(roi_w, RCP7);

    int hs = (int)floorf(__fmul_rn((float)ph, bh)) + rsh;
    int he = (int)ceilf (__fmul_rn((float)ph + 1.0f, bh)) + rsh;
    hs = min(max(hs, 0), HH);
    he = min(max(he, 0), HH);

    int wlo = min(max(rsw, 0), WW);
    int whi = min(max((int)ceilf(__fmul_rn(7.0f, bw)) + rsw, 0), WW);

    int b = __ldg(&roibatches[n]);
    const float4* base = (const float4*)(g_dt + (size_t)b * HW * CC);
    int coff = chalf * 32;             // c4 offset within CC/4=64

    // ---- Phase A: colmax over rows (each element loaded once) ----
    if (he > hs) {
        int ncols = whi - wlo;
        for (int k = slice; k < ncols; k += 4) {
            int col = wlo + k;
            float4 m = make_float4(-CUDART_INF_F, -CUDART_INF_F,
                                   -CUDART_INF_F, -CUDART_INF_F);
            const float4* p = base + ((size_t)hs * WW + col) * (CC / 4)
                                   + coff + c4;
            for (int h = hs; h < he; ++h) {
                float4 v = __ldg(p);
                m.x = fmaxf(m.x, v.x);
                m.y = fmaxf(m.y, v.y);
                m.z = fmaxf(m.z, v.z);
                m.w = fmaxf(m.w, v.w);
                p += WW * (CC / 4);
            }
            sm[k][c4] = m;
        }
    }
    __syncthreads();

    // ---- Phase B: pw windows reduce over colmax ----
    for (int task = threadIdx.x; task < CROP_W * 32; task += 128) {
        int pw  = task >> 5;
        int c4i = task & 31;

        int ws = (int)floorf(__fmul_rn((float)pw, bw)) + rsw;
        int we = (int)ceilf (__fmul_rn((float)pw + 1.0f, bw)) + rsw;
        ws = min(max(ws, 0), WW);
        we = min(max(we, 0), WW);

        float4 m;
        if (he <= hs || we <= ws) {
            m = make_float4(0.f, 0.f, 0.f, 0.f);
        } else {
            m = make_float4(-CUDART_INF_F, -CUDART_INF_F,
                            -CUDART_INF_F, -CUDART_INF_F);
            for (int k = ws - wlo; k < we - wlo; ++k) {
                float4 v = sm[k][c4i];
                m.x = fmaxf(m.x, v.x);
                m.y = fmaxf(m.y, v.y);
                m.z = fmaxf(m.z, v.z);
                m.w = fmaxf(m.w, v.w);
            }
        }

        int c0 = (coff + c4i) * 4;
        size_t ob = (((size_t)n * CC + c0) * CROP_H + ph) * CROP_W + pw;
        const size_t cs = CROP_H * CROP_W;
        out[ob]          = m.x;
        out[ob + cs]     = m.y;
        out[ob + 2 * cs] = m.z;
        out[ob + 3 * cs] = m.w;
    }
}

extern "C" void kernel_launch(void* const* d_in, const int* in_sizes, int n_in,
                              void* d_out, int out_size)
{
    const float* data      = nullptr;
    const float* rois      = nullptr;
    const int*   batches   = nullptr;
    const float* scale_ptr = nullptr;

    for (int i = 0; i < n_in; ++i) {
        int sz = in_sizes[i];
        if (sz == 1)            scale_ptr = (const float*)d_in[i];
        else if (sz == 128)     batches   = (const int*)d_in[i];
        else if (sz == 512)     rois      = (const float*)d_in[i];
        else                    data      = (const float*)d_in[i];
    }

    float* out = (float*)d_out;

    dim3 tgrid(HW / 32, CC / 32, BB);     // 128 x 8 x 4 = 4096 blocks
    dim3 tblock(32, 8);
    transpose_kernel<<<tgrid, tblock>>>(data);

    dim3 pgrid(CROP_H * 2, NROI);         // 14 x 128 = 1792 blocks
    pool_kernel<<<pgrid, 128>>>(rois, batches, scale_ptr, out);
}

// round 14
// speedup vs baseline: 1.1204x; 1.1204x over previous
#include <cuda_runtime.h>
#include <cuda_bf16.h>
#include <math_constants.h>

// RoI max pooling (Caffe-style), bit-matching the JAX/XLA:CPU reference.
// VERIFIED ARITHMETIC (R6, rel_err==0.0) — do not alter:
//   rs*    = rintf(__fmul_rn(coord, scale))
//   bh/bw  = __fmul_rn(roi_extent, 1.0f/7.0f)   (XLA fast-math reciprocal form)
//   hstart = floorf(__fmul_rn(ph, bh)) + rsh ; hend = ceilf(__fmul_rn(ph+1,bh)) + rsh
//   clip to [0,64]; empty bin (hend<=hstart || wend<=wstart) -> 0.
//
// Kernel 1: transpose [B,C,H*W] -> [B,H*W,C]  +  (block 0) per-roi geometry
//           tables — removes the per-thread geometry prologue that kept the
//           R12 pool at issue=54% / L2=40% (latency-bound on rois->SFU chain).
// Kernel 2: pool. Block = (n, ph, pw), 256 thr = 64 c4-lanes x 4 element
//           slices; float4 loads from channel-fastest scratch; smem reduce.

#define CROP_H 7
#define CROP_W 7
#define NROI   128
#define HH     64
#define WW     64
#define HW     (HH * WW)
#define CC     256
#define BB     4
#define NSLICE 4

__device__ float g_dt[BB * HW * CC];     // 16 MB transposed data
__device__ int   g_hs[NROI * CROP_H];
__device__ int   g_he[NROI * CROP_H];
__device__ int   g_ws[NROI * CROP_W];
__device__ int   g_we[NROI * CROP_W];
__device__ int   g_base4[NROI];          // batch * HW * (CC/4)

// ------- transpose [b][c][hw] -> [b][hw][c], + geometry setup in block 0 -------
__global__ __launch_bounds__(256)
void transpose_kernel(const float* __restrict__ in,
                      const float* __restrict__ rois,
                      const int*   __restrict__ roibatches,
                      const float* __restrict__ scale_ptr)
{
    // ---- geometry tables (one roi per thread; verified arithmetic) ----
    if (blockIdx.x == 0 && blockIdx.y == 0 && blockIdx.z == 0) {
        int tid = threadIdx.y * 32 + threadIdx.x;
        if (tid < NROI) {
            int n = tid;
            float scale = scale_ptr[0];
            float x1 = rois[n * 4 + 0];
            float y1 = rois[n * 4 + 1];
            float x2 = rois[n * 4 + 2];
            float y2 = rois[n * 4 + 3];

            int rsw = (int)rintf(__fmul_rn(x1, scale));
            int rsh = (int)rintf(__fmul_rn(y1, scale));
            int rew = (int)rintf(__fmul_rn(x2, scale));
            int reh = (int)rintf(__fmul_rn(y2, scale));

            float roi_h = (float)max(reh - rsh + 1, 1);
            float roi_w = (float)max(rew - rsw + 1, 1);
            const float RCP7 = 1.0f / 7.0f;
            float bh = __fmul_rn(roi_h, RCP7);
            float bw = __fmul_rn(roi_w, RCP7);

            #pragma unroll
            for (int p = 0; p < CROP_H; ++p) {
                int hs = (int)floorf(__fmul_rn((float)p, bh)) + rsh;
                int he = (int)ceilf (__fmul_rn((float)p + 1.0f, bh)) + rsh;
                g_hs[n * CROP_H + p] = min(max(hs, 0), HH);
                g_he[n * CROP_H + p] = min(max(he, 0), HH);

                int ws = (int)floorf(__fmul_rn((float)p, bw)) + rsw;
                int we = (int)ceilf (__fmul_rn((float)p + 1.0f, bw)) + rsw;
                g_ws[n * CROP_W + p] = min(max(ws, 0), WW);
                g_we[n * CROP_W + p] = min(max(we, 0), WW);
            }
            g_base4[n] = roibatches[n] * HW * (CC / 4);
        }
    }

    // ---- transpose tile ----
    __shared__ float tile[32][33];
    int b   = blockIdx.z;
    int hw0 = blockIdx.x * 32;
    int c0  = blockIdx.y * 32;

    const float* src = in   + (size_t)b * CC * HW;
    float*       dst = g_dt + (size_t)b * HW * CC;

    #pragma unroll
    for (int i = threadIdx.y; i < 32; i += 8)
        tile[i][threadIdx.x] = src[(size_t)(c0 + i) * HW + hw0 + threadIdx.x];
    __syncthreads();
    #pragma unroll
    for (int i = threadIdx.y; i < 32; i += 8)
        dst[(size_t)(hw0 + i) * CC + c0 + threadIdx.x] = tile[threadIdx.x][i];
}

// -------- pool: block = (n, ph, pw); 64 c4-lanes x 4 element-slices --------
__global__ __launch_bounds__(256)
void pool_kernel(float* __restrict__ out)
{
    __shared__ float4 sm[NSLICE][CC / 4];

    int bi = blockIdx.x;
    int pw = bi % CROP_W;
    int t  = bi / CROP_W;
    int ph = t % CROP_H;
    int n  = t / CROP_H;

    int c4    = threadIdx.x & 63;
    int slice = threadIdx.x >> 6;

    // tiny prologue: 5 uniform table loads (warp-broadcast)
    int hs = g_hs[n * CROP_H + ph];
    int he = g_he[n * CROP_H + ph];
    int ws = g_ws[n * CROP_W + pw];
    int we = g_we[n * CROP_W + pw];

    bool empty = (he <= hs) || (we <= ws);
    unsigned wspan = empty ? 1u : (unsigned)(we - ws);
    unsigned E     = empty ? 0u : wspan * (unsigned)(he - hs);

    const float4* base = (const float4*)g_dt + g_base4[n];

    float4 m = make_float4(-CUDART_INF_F, -CUDART_INF_F,
                           -CUDART_INF_F, -CUDART_INF_F);

    for (unsigned e = slice; e < E; e += NSLICE) {
        unsigned dh = e / wspan;
        unsigned dw = e - dh * wspan;
        const float4* p = base + ((size_t)((hs + dh) * WW + ws + dw)) * (CC / 4) + c4;
        float4 v = __ldg(p);
        m.x = fmaxf(m.x, v.x);
        m.y = fmaxf(m.y, v.y);
        m.z = fmaxf(m.z, v.z);
        m.w = fmaxf(m.w, v.w);
    }

    sm[slice][c4] = m;
    __syncthreads();

    if (slice == 0) {
        float4 a = sm[0][c4], b1 = sm[1][c4], c2 = sm[2][c4], d = sm[3][c4];
        m.x = fmaxf(fmaxf(a.x, b1.x), fmaxf(c2.x, d.x));
        m.y = fmaxf(fmaxf(a.y, b1.y), fmaxf(c2.y, d.y));
        m.z = fmaxf(fmaxf(a.z, b1.z), fmaxf(c2.z, d.z));
        m.w = fmaxf(fmaxf(a.w, b1.w), fmaxf(c2.w, d.w));
        if (empty) m = make_float4(0.f, 0.f, 0.f, 0.f);

        int c0 = c4 * 4;
        size_t ob = (((size_t)n * CC + c0) * CROP_H + ph) * CROP_W + pw;
        const size_t cs = CROP_H * CROP_W;
        out[ob]          = m.x;
        out[ob + cs]     = m.y;
        out[ob + 2 * cs] = m.z;
        out[ob + 3 * cs] = m.w;
    }
}

extern "C" void kernel_launch(void* const* d_in, const int* in_sizes, int n_in,
                              void* d_out, int out_size)
{
    const float* data      = nullptr;
    const float* rois      = nullptr;
    const int*   batches   = nullptr;
    const float* scale_ptr = nullptr;

    for (int i = 0; i < n_in; ++i) {
        int sz = in_sizes[i];
        if (sz == 1)            scale_ptr = (const float*)d_in[i];
        else if (sz == 128)     batches   = (const int*)d_in[i];
        else if (sz == 512)     rois      = (const float*)d_in[i];
        else                    data      = (const float*)d_in[i];
    }

    float* out = (float*)d_out;

    dim3 tgrid(HW / 32, CC / 32, BB);     // 128 x 8 x 4 = 4096 blocks
    dim3 tblock(32, 8);
    transpose_kernel<<<tgrid, tblock>>>(data, rois, batches, scale_ptr);

    pool_kernel<<<NROI * CROP_H * CROP_W, 256>>>(out);
}

// round 15
// speedup vs baseline: 1.2068x; 1.0771x over previous
#include <cuda_runtime.h>
#include <cuda_bf16.h>
#include <math_constants.h>

// RoI max pooling (Caffe-style), bit-matching the JAX/XLA:CPU reference.
// VERIFIED ARITHMETIC (R6, rel_err==0.0) — do not alter:
//   rs*    = rintf(__fmul_rn(coord, scale))
//   bh/bw  = __fmul_rn(roi_extent, 1.0f/7.0f)   (XLA fast-math reciprocal form)
//   hstart = floorf(__fmul_rn(ph, bh)) + rsh ; hend = ceilf(__fmul_rn(ph+1,bh)) + rsh
//   clip to [0,64]; empty bin (hend<=hstart || wend<=wstart) -> 0.
//
// Kernel 1: float4 transpose [B,C,H*W] -> [B,H*W,C] + geometry tables (blk 0).
// Kernel 2: pool. Block = (n, ph, pw), 128 thr = 32 c4-lanes x 4 element
//   slices; each thread loads TWO float4s per window element (channel quads
//   c4 and c4+32) -> ~2x per-thread MLP vs R14 (L2 was stuck at 39% because
//   threads issued only ~3 loads before the barrier). Same bytes, higher
//   duty cycle; 128-thr blocks -> 16 resident blocks/SM for tail packing.

#define CROP_H 7
#define CROP_W 7
#define NROI   128
#define HH     64
#define WW     64
#define HW     (HH * WW)
#define CC     256
#define BB     4
#define NSLICE 4

__device__ float g_dt[BB * HW * CC];     // 16 MB transposed data
__device__ int   g_hs[NROI * CROP_H];
__device__ int   g_he[NROI * CROP_H];
__device__ int   g_ws[NROI * CROP_W];
__device__ int   g_we[NROI * CROP_W];
__device__ int   g_base4[NROI];          // batch * HW * (CC/4)

// ------- transpose [b][c][hw] -> [b][hw][c] (float4 both ways) + setup -------
__global__ __launch_bounds__(256)
void transpose_kernel(const float* __restrict__ in,
                      const float* __restrict__ rois,
                      const int*   __restrict__ roibatches,
                      const float* __restrict__ scale_ptr)
{
    // ---- geometry tables (one roi per thread; verified arithmetic) ----
    if (blockIdx.x == 0 && blockIdx.y == 0 && blockIdx.z == 0) {
        int tid = threadIdx.y * 8 + threadIdx.x;
        if (tid < NROI) {
            int n = tid;
            float scale = scale_ptr[0];
            float x1 = rois[n * 4 + 0];
            float y1 = rois[n * 4 + 1];
            float x2 = rois[n * 4 + 2];
            float y2 = rois[n * 4 + 3];

            int rsw = (int)rintf(__fmul_rn(x1, scale));
            int rsh = (int)rintf(__fmul_rn(y1, scale));
            int rew = (int)rintf(__fmul_rn(x2, scale));
            int reh = (int)rintf(__fmul_rn(y2, scale));

            float roi_h = (float)max(reh - rsh + 1, 1);
            float roi_w = (float)max(rew - rsw + 1, 1);
            const float RCP7 = 1.0f / 7.0f;
            float bh = __fmul_rn(roi_h, RCP7);
            float bw = __fmul_rn(roi_w, RCP7);

            #pragma unroll
            for (int p = 0; p < CROP_H; ++p) {
                int hs = (int)floorf(__fmul_rn((float)p, bh)) + rsh;
                int he = (int)ceilf (__fmul_rn((float)p + 1.0f, bh)) + rsh;
                g_hs[n * CROP_H + p] = min(max(hs, 0), HH);
                g_he[n * CROP_H + p] = min(max(he, 0), HH);

                int ws = (int)floorf(__fmul_rn((float)p, bw)) + rsw;
                int we = (int)ceilf (__fmul_rn((float)p + 1.0f, bw)) + rsw;
                g_ws[n * CROP_W + p] = min(max(ws, 0), WW);
                g_we[n * CROP_W + p] = min(max(we, 0), WW);
            }
            g_base4[n] = roibatches[n] * HW * (CC / 4);
        }
    }

    // ---- 32x32 tile transpose, float4 loads and stores ----
    __shared__ float tile[32][33];
    int b   = blockIdx.z;
    int hw0 = blockIdx.x * 32;
    int c0  = blockIdx.y * 32;
    int tx  = threadIdx.x;     // 0..7
    int ty  = threadIdx.y;     // 0..31

    const float4* src4 = (const float4*)(in + (size_t)b * CC * HW);
    float4*       dst4 = (float4*)(g_dt + (size_t)b * HW * CC);

    // load: row = channel c0+ty, 4 hw positions per thread
    {
        float4 v = src4[((size_t)(c0 + ty) * HW + hw0) / 4 + tx];
        tile[ty][tx * 4 + 0] = v.x;
        tile[ty][tx * 4 + 1] = v.y;
        tile[ty][tx * 4 + 2] = v.z;
        tile[ty][tx * 4 + 3] = v.w;
    }
    __syncthreads();
    // store: row = hw position hw0+ty, 4 channels per thread (bank-conflict-free)
    {
        float4 v;
        v.x = tile[tx * 4 + 0][ty];
        v.y = tile[tx * 4 + 1][ty];
        v.z = tile[tx * 4 + 2][ty];
        v.w = tile[tx * 4 + 3][ty];
        dst4[((size_t)(hw0 + ty) * CC + c0) / 4 + tx] = v;
    }
}

// ---- pool: block = (n, ph, pw); 32 c4-lanes x 4 slices, 2 quads/thread ----
__global__ __launch_bounds__(128)
void pool_kernel(float* __restrict__ out)
{
    __shared__ float4 sm[NSLICE][CC / 4];   // 4 KB

    int bi = blockIdx.x;
    int pw = bi % CROP_W;
    int t  = bi / CROP_W;
    int ph = t % CROP_H;
    int n  = t / CROP_H;

    int lane  = threadIdx.x & 31;   // c4 lane (quads lane and lane+32)
    int slice = threadIdx.x >> 5;   // 0..3

    int hs = g_hs[n * CROP_H + ph];
    int he = g_he[n * CROP_H + ph];
    int ws = g_ws[n * CROP_W + pw];
    int we = g_we[n * CROP_W + pw];

    bool empty = (he <= hs) || (we <= ws);
    unsigned wspan = empty ? 1u : (unsigned)(we - ws);
    unsigned E     = empty ? 0u : wspan * (unsigned)(he - hs);

    const float4* base = (const float4*)g_dt + g_base4[n];

    float4 ma = make_float4(-CUDART_INF_F, -CUDART_INF_F,
                            -CUDART_INF_F, -CUDART_INF_F);
    float4 mb = ma;

    for (unsigned e = slice; e < E; e += NSLICE) {
        unsigned dh = e / wspan;
        unsigned dw = e - dh * wspan;
        const float4* p = base + ((size_t)((hs + dh) * WW + ws + dw)) * (CC / 4);
        float4 va = __ldg(p + lane);
        float4 vb = __ldg(p + lane + 32);
        ma.x = fmaxf(ma.x, va.x); ma.y = fmaxf(ma.y, va.y);
        ma.z = fmaxf(ma.z, va.z); ma.w = fmaxf(ma.w, va.w);
        mb.x = fmaxf(mb.x, vb.x); mb.y = fmaxf(mb.y, vb.y);
        mb.z = fmaxf(mb.z, vb.z); mb.w = fmaxf(mb.w, vb.w);
    }

    sm[slice][lane]      = ma;
    sm[slice][lane + 32] = mb;
    __syncthreads();

    if (threadIdx.x < 64) {
        int c4 = threadIdx.x;
        float4 a = sm[0][c4], b1 = sm[1][c4], c2 = sm[2][c4], d = sm[3][c4];
        float4 m;
        m.x = fmaxf(fmaxf(a.x, b1.x), fmaxf(c2.x, d.x));
        m.y = fmaxf(fmaxf(a.y, b1.y), fmaxf(c2.y, d.y));
        m.z = fmaxf(fmaxf(a.z, b1.z), fmaxf(c2.z, d.z));
        m.w = fmaxf(fmaxf(a.w, b1.w), fmaxf(c2.w, d.w));
        if (empty) m = make_float4(0.f, 0.f, 0.f, 0.f);

        int c0 = c4 * 4;
        size_t ob = (((size_t)n * CC + c0) * CROP_H + ph) * CROP_W + pw;
        const size_t cs = CROP_H * CROP_W;
        out[ob]          = m.x;
        out[ob + cs]     = m.y;
        out[ob + 2 * cs] = m.z;
        out[ob + 3 * cs] = m.w;
    }
}

extern "C" void kernel_launch(void* const* d_in, const int* in_sizes, int n_in,
                              void* d_out, int out_size)
{
    const float* data      = nullptr;
    const float* rois      = nullptr;
    const int*   batches   = nullptr;
    const float* scale_ptr = nullptr;

    for (int i = 0; i < n_in; ++i) {
        int sz = in_sizes[i];
        if (sz == 1)            scale_ptr = (const float*)d_in[i];
        else if (sz == 128)     batches   = (const int*)d_in[i];
        else if (sz == 512)     rois      = (const float*)d_in[i];
        else                    data      = (const float*)d_in[i];
    }

    float* out = (float*)d_out;

    dim3 tgrid(HW / 32, CC / 32, BB);     // 128 x 8 x 4 = 4096 blocks
    dim3 tblock(8, 32);                   // 256 threads, float4 both ways
    transpose_kernel<<<tgrid, tblock>>>(data, rois, batches, scale_ptr);

    pool_kernel<<<NROI * CROP_H * CROP_W, 128>>>(out);
}

// round 17
// speedup vs baseline: 1.2110x; 1.0035x over previous
#include <cuda_runtime.h>
#include <cuda_bf16.h>
#include <math_constants.h>

// RoI max pooling (Caffe-style), bit-matching the JAX/XLA:CPU reference.
// VERIFIED ARITHMETIC (R6, rel_err==0.0) — do not alter:
//   rs*    = rintf(__fmul_rn(coord, scale))
//   bh/bw  = __fmul_rn(roi_extent, 1.0f/7.0f)   (XLA fast-math reciprocal form)
//   hstart = floorf(__fmul_rn(ph, bh)) + rsh ; hend = ceilf(__fmul_rn(ph+1,bh)) + rsh
//   clip to [0,64]; empty bin (hend<=hstart || wend<=wstart) -> 0.
//
// R17 = R16 with the wspan==1 divider bug fixed: magic = 0xFFFFFFFF/1+1
// overflowed to 0, sending single-column windows sideways (rel_err 0.17).
// Now dh = (wspan==1) ? ee : __umulhi(ee, magic) — uniform select, exact.
// Batched loads (4 elements x 2 quads issued back-to-back before reducing)
// unchanged: that's the MLP fix for the load->fmax serialization that held
// L2 at 40%.

#define CROP_H 7
#define CROP_W 7
#define NROI   128
#define HH     64
#define WW     64
#define HW     (HH * WW)
#define CC     256
#define BB     4
#define NSLICE 4
#define BATCH  4

__device__ float g_dt[BB * HW * CC];            // 16 MB transposed data
__device__ int4  g_bins[NROI * CROP_H * CROP_W]; // packed hs,he,ws,we per bin
__device__ int   g_base4[NROI];                  // batch * HW * (CC/4)

// ------- transpose [b][c][hw] -> [b][hw][c] (float4 both ways) + setup -------
__global__ __launch_bounds__(256)
void transpose_kernel(const float* __restrict__ in,
                      const float* __restrict__ rois,
                      const int*   __restrict__ roibatches,
                      const float* __restrict__ scale_ptr)
{
    // ---- geometry tables (one roi per thread; verified arithmetic) ----
    if (blockIdx.x == 0 && blockIdx.y == 0 && blockIdx.z == 0) {
        int tid = threadIdx.y * 8 + threadIdx.x;
        if (tid < NROI) {
            int n = tid;
            float scale = scale_ptr[0];
            float x1 = rois[n * 4 + 0];
            float y1 = rois[n * 4 + 1];
            float x2 = rois[n * 4 + 2];
            float y2 = rois[n * 4 + 3];

            int rsw = (int)rintf(__fmul_rn(x1, scale));
            int rsh = (int)rintf(__fmul_rn(y1, scale));
            int rew = (int)rintf(__fmul_rn(x2, scale));
            int reh = (int)rintf(__fmul_rn(y2, scale));

            float roi_h = (float)max(reh - rsh + 1, 1);
            float roi_w = (float)max(rew - rsw + 1, 1);
            const float RCP7 = 1.0f / 7.0f;
            float bh = __fmul_rn(roi_h, RCP7);
            float bw = __fmul_rn(roi_w, RCP7);

            int hsa[CROP_H], hea[CROP_H], wsa[CROP_W], wea[CROP_W];
            #pragma unroll
            for (int p = 0; p < CROP_H; ++p) {
                int hs = (int)floorf(__fmul_rn((float)p, bh)) + rsh;
                int he = (int)ceilf (__fmul_rn((float)p + 1.0f, bh)) + rsh;
                hsa[p] = min(max(hs, 0), HH);
                hea[p] = min(max(he, 0), HH);

                int ws = (int)floorf(__fmul_rn((float)p, bw)) + rsw;
                int we = (int)ceilf (__fmul_rn((float)p + 1.0f, bw)) + rsw;
                wsa[p] = min(max(ws, 0), WW);
                wea[p] = min(max(we, 0), WW);
            }
            #pragma unroll
            for (int ph = 0; ph < CROP_H; ++ph)
                #pragma unroll
                for (int pw = 0; pw < CROP_W; ++pw)
                    g_bins[(n * CROP_H + ph) * CROP_W + pw] =
                        make_int4(hsa[ph], hea[ph], wsa[pw], wea[pw]);

            g_base4[n] = roibatches[n] * HW * (CC / 4);
        }
    }

    // ---- 32x32 tile transpose, float4 loads and stores ----
    __shared__ float tile[32][33];
    int b   = blockIdx.z;
    int hw0 = blockIdx.x * 32;
    int c0  = blockIdx.y * 32;
    int tx  = threadIdx.x;     // 0..7
    int ty  = threadIdx.y;     // 0..31

    const float4* src4 = (const float4*)(in + (size_t)b * CC * HW);
    float4*       dst4 = (float4*)(g_dt + (size_t)b * HW * CC);

    {
        float4 v = src4[((size_t)(c0 + ty) * HW + hw0) / 4 + tx];
        tile[ty][tx * 4 + 0] = v.x;
        tile[ty][tx * 4 + 1] = v.y;
        tile[ty][tx * 4 + 2] = v.z;
        tile[ty][tx * 4 + 3] = v.w;
    }
    __syncthreads();
    {
        float4 v;
        v.x = tile[tx * 4 + 0][ty];
        v.y = tile[tx * 4 + 1][ty];
        v.z = tile[tx * 4 + 2][ty];
        v.w = tile[tx * 4 + 3][ty];
        dst4[((size_t)(hw0 + ty) * CC + c0) / 4 + tx] = v;
    }
}

__device__ __forceinline__ void fmax4(float4& a, const float4& v)
{
    a.x = fmaxf(a.x, v.x);
    a.y = fmaxf(a.y, v.y);
    a.z = fmaxf(a.z, v.z);
    a.w = fmaxf(a.w, v.w);
}

// ---- pool: block = bin (n,ph,pw); 32 c4-lanes x 4 slices; batched loads ----
__global__ __launch_bounds__(128)
void pool_kernel(float* __restrict__ out)
{
    __shared__ float4 sm[NSLICE][CC / 4];   // 4 KB

    int bi = blockIdx.x;
    int n  = bi / (CROP_H * CROP_W);

    int lane  = threadIdx.x & 31;   // c4 lane (quads lane and lane+32)
    int slice = threadIdx.x >> 5;   // 0..3

    int4 bb = __ldg(&g_bins[bi]);
    int hs = bb.x, he = bb.y, ws = bb.z, we = bb.w;

    bool empty = (he <= hs) || (we <= ws);
    unsigned wspan = empty ? 1u : (unsigned)(we - ws);
    unsigned E     = empty ? 0u : wspan * (unsigned)(he - hs);
    bool w1 = (wspan == 1u);                     // magic overflows for d=1
    unsigned magic = 0xFFFFFFFFu / wspan + 1u;   // exact for 2<=d, e<2^16

    const float4* base = (const float4*)g_dt + g_base4[n] + lane;
    int pixbase = hs * WW + ws;

    float4 ma = make_float4(-CUDART_INF_F, -CUDART_INF_F,
                            -CUDART_INF_F, -CUDART_INF_F);
    float4 mb = ma;

    for (unsigned e = slice; e < E; e += BATCH * NSLICE) {
        float4 va[BATCH], vb[BATCH];
        bool   pr[BATCH];
        // issue all loads back-to-back (independent of the accumulator)
        #pragma unroll
        for (int j = 0; j < BATCH; ++j) {
            unsigned ee = e + (unsigned)j * NSLICE;
            pr[j] = ee < E;
            unsigned dh = w1 ? ee : __umulhi(ee, magic);
            unsigned dw = ee - dh * wspan;
            const float4* p = base + (size_t)(pixbase + dh * WW + dw) * (CC / 4);
            if (pr[j]) {
                va[j] = __ldg(p);
                vb[j] = __ldg(p + 32);
            }
        }
        // then reduce
        #pragma unroll
        for (int j = 0; j < BATCH; ++j) {
            if (pr[j]) {
                fmax4(ma, va[j]);
                fmax4(mb, vb[j]);
            }
        }
    }

    sm[slice][lane]      = ma;
    sm[slice][lane + 32] = mb;
    __syncthreads();

    if (threadIdx.x < 64) {
        int c4 = threadIdx.x;
        float4 a = sm[0][c4], b1 = sm[1][c4], c2 = sm[2][c4], d = sm[3][c4];
        float4 m;
        m.x = fmaxf(fmaxf(a.x, b1.x), fmaxf(c2.x, d.x));
        m.y = fmaxf(fmaxf(a.y, b1.y), fmaxf(c2.y, d.y));
        m.z = fmaxf(fmaxf(a.z, b1.z), fmaxf(c2.z, d.z));
        m.w = fmaxf(fmaxf(a.w, b1.w), fmaxf(c2.w, d.w));
        if (empty) m = make_float4(0.f, 0.f, 0.f, 0.f);

        int pw = bi % CROP_W;
        int ph = (bi / CROP_W) % CROP_H;
        int c0 = c4 * 4;
        size_t ob = (((size_t)n * CC + c0) * CROP_H + ph) * CROP_W + pw;
        const size_t cs = CROP_H * CROP_W;
        out[ob]          = m.x;
        out[ob + cs]     = m.y;
        out[ob + 2 * cs] = m.z;
        out[ob + 3 * cs] = m.w;
    }
}

extern "C" void kernel_launch(void* const* d_in, const int* in_sizes, int n_in,
                              void* d_out, int out_size)
{
    const float* data      = nullptr;
    const float* rois      = nullptr;
    const int*   batches   = nullptr;
    const float* scale_ptr = nullptr;

    for (int i = 0; i < n_in; ++i) {
        int sz = in_sizes[i];
        if (sz == 1)            scale_ptr = (const float*)d_in[i];
        else if (sz == 128)     batches   = (const int*)d_in[i];
        else if (sz == 512)     rois      = (const float*)d_in[i];
        else                    data      = (const float*)d_in[i];
    }

    float* out = (float*)d_out;

    dim3 tgrid(HW / 32, CC / 32, BB);     // 128 x 8 x 4 = 4096 blocks
    dim3 tblock(8, 32);                   // 256 threads, float4 both ways
    transpose_kernel<<<tgrid, tblock>>>(data, rois, batches, scale_ptr);

    pool_kernel<<<NROI * CROP_H * CROP_W, 128>>>(out);
}